// round 2
// baseline (speedup 1.0000x reference)
#include <cuda_runtime.h>
#include <stdint.h>

// Problem constants
static const int kC    = 256;
static const int kHW   = 65536;   // H*W per channel
static const int kL    = 3;
static const int kSegs = 768;     // 3 levels * 256 channels
static const int kBins = 256;

// Scratch (device globals; no allocation allowed)
__device__ unsigned int g_bufA[(size_t)kSegs * kHW]; // 192 MB
__device__ unsigned int g_bufB[(size_t)kSegs * kHW]; // 192 MB
__device__ double       g_S1[kL];
__device__ double       g_S2[kL];
__device__ unsigned int g_Mc[kC];

// Order-preserving float->u32 transform, mask bit stuffed into LSB.
__device__ __forceinline__ unsigned int key_xform(float f, int m) {
    unsigned int u = __float_as_uint(f);
    u = (u & 0x80000000u) ? ~u : (u | 0x80000000u);
    return (u & ~1u) | (m != 0 ? 1u : 0u);
}

__global__ void init_kernel() {
    int t = threadIdx.x;
    if (t < kL) { g_S1[t] = 0.0; g_S2[t] = 0.0; }
    if (t < kC) g_Mc[t] = 0u;
}

// Build keys + masked sums. grid = (8, 768), 256 threads. 8192 elems/block.
__global__ void build_kernel(const float* __restrict__ opt0,
                             const float* __restrict__ opt1,
                             const float* __restrict__ opt2,
                             const int*  __restrict__ mask) {
    int seg = blockIdx.y;
    int l = seg >> 8;
    int c = seg & 255;
    const float* opt = (l == 0) ? opt0 : (l == 1) ? opt1 : opt2;
    const float4* optv = reinterpret_cast<const float4*>(opt) + (size_t)c * (kHW / 4);
    const int4*   mv   = reinterpret_cast<const int4*>(mask)  + (size_t)c * (kHW / 4);
    uint4* dstv = reinterpret_cast<uint4*>(g_bufA + (size_t)seg * kHW);

    int base = blockIdx.x * 2048; // in float4 units
    float fsum = 0.f;
    int   msum = 0;
#pragma unroll
    for (int i = 0; i < 8; i++) {
        int vi = base + i * 256 + threadIdx.x;
        float4 v = optv[vi];
        int4   m = mv[vi];
        uint4 k;
        k.x = key_xform(v.x, m.x);
        k.y = key_xform(v.y, m.y);
        k.z = key_xform(v.z, m.z);
        k.w = key_xform(v.w, m.w);
        dstv[vi] = k;
        if (m.x) { fsum += v.x; msum++; }
        if (m.y) { fsum += v.y; msum++; }
        if (m.z) { fsum += v.z; msum++; }
        if (m.w) { fsum += v.w; msum++; }
    }
    __shared__ float sf[8];
    __shared__ int   si[8];
    int lane = threadIdx.x & 31, warp = threadIdx.x >> 5;
#pragma unroll
    for (int off = 16; off > 0; off >>= 1) {
        fsum += __shfl_down_sync(0xFFFFFFFFu, fsum, off);
        msum += __shfl_down_sync(0xFFFFFFFFu, msum, off);
    }
    if (lane == 0) { sf[warp] = fsum; si[warp] = msum; }
    __syncthreads();
    if (warp == 0) {
        float f  = (lane < 8) ? sf[lane] : 0.f;
        int   mi = (lane < 8) ? si[lane] : 0;
#pragma unroll
        for (int off = 16; off > 0; off >>= 1) {
            f  += __shfl_down_sync(0xFFFFFFFFu, f,  off);
            mi += __shfl_down_sync(0xFFFFFFFFu, mi, off);
        }
        if (lane == 0) {
            atomicAdd(&g_S1[l], (double)f);
            if (l == 0) atomicAdd(&g_Mc[c], (unsigned int)mi);
        }
    }
}

// Per-segment 4-pass LSD radix sort (8-bit digits), one CTA per segment.
// Stable scatter: per-tile u16 histograms + match_any warp ranking.
__global__ void __launch_bounds__(1024, 2) sort_kernel() {
    __shared__ unsigned short tileHist[64 * 256]; // 32 KB, counts/positions fit u16
    __shared__ unsigned int   digitStart[256];

    int seg = blockIdx.x;
    unsigned int* A = g_bufA + (size_t)seg * kHW;
    unsigned int* B = g_bufB + (size_t)seg * kHW;
    int tid  = threadIdx.x;
    int warp = tid >> 5, lane = tid & 31;
    unsigned int lt_mask = (1u << lane) - 1u;

    for (int pass = 0; pass < 4; pass++) {
        int shift = pass * 8;
        unsigned int* src = (pass & 1) ? B : A;
        unsigned int* dst = (pass & 1) ? A : B;

        // zero tile histograms (32KB = 8192 u32 words)
        for (int i = tid; i < 8192; i += 1024)
            reinterpret_cast<unsigned int*>(tileHist)[i] = 0u;
        __syncthreads();

        // Phase A: per-tile digit histograms. Warp w owns tiles w and w+32.
        for (int t = warp; t < 64; t += 32) {
            unsigned short* h = tileHist + t * 256;
            int tb = t * 1024;
            for (int it = 0; it < 32; it++) {
                unsigned int key = src[tb + it * 32 + lane];
                unsigned int d = (key >> shift) & 255u;
                unsigned int mm = __match_any_sync(0xFFFFFFFFu, d);
                int leader = __ffs(mm) - 1;
                if (lane == leader)
                    h[d] = (unsigned short)(h[d] + (unsigned short)__popc(mm));
                __syncwarp();
            }
        }
        __syncthreads();

        // Per-digit exclusive prefix over tiles + digit totals
        if (tid < 256) {
            unsigned int run = 0;
            for (int t = 0; t < 64; t++) {
                unsigned int v = tileHist[t * 256 + tid];
                tileHist[t * 256 + tid] = (unsigned short)run;
                run += v;
            }
            digitStart[tid] = run; // temporarily: total count for this digit
        }
        __syncthreads();

        // Exclusive scan of 256 digit totals (one warp, 8 digits/lane)
        if (warp == 0) {
            unsigned int v[8], s = 0;
#pragma unroll
            for (int j = 0; j < 8; j++) { v[j] = digitStart[lane * 8 + j]; s += v[j]; }
            unsigned int incl = s;
#pragma unroll
            for (int off = 1; off < 32; off <<= 1) {
                unsigned int o = __shfl_up_sync(0xFFFFFFFFu, incl, off);
                if (lane >= off) incl += o;
            }
            unsigned int excl = incl - s;
#pragma unroll
            for (int j = 0; j < 8; j++) { digitStart[lane * 8 + j] = excl; excl += v[j]; }
        }
        __syncthreads();

        // Fold digit bases into tile prefixes -> absolute scatter bases
        if (tid < 256) {
            unsigned int ds = digitStart[tid];
            for (int t = 0; t < 64; t++)
                tileHist[t * 256 + tid] =
                    (unsigned short)(tileHist[t * 256 + tid] + ds);
        }
        __syncthreads();

        // Phase B: stable scatter
        for (int t = warp; t < 64; t += 32) {
            unsigned short* h = tileHist + t * 256;
            int tb = t * 1024;
            for (int it = 0; it < 32; it++) {
                unsigned int key = src[tb + it * 32 + lane];
                unsigned int d = (key >> shift) & 255u;
                unsigned int mm = __match_any_sync(0xFFFFFFFFu, d);
                int leader = __ffs(mm) - 1;
                unsigned int rank = __popc(mm & lt_mask);
                unsigned int basepos = h[d]; // all lanes read (broadcast/dup ok)
                dst[basepos + rank] = key;
                if (lane == leader)
                    h[d] = (unsigned short)(basepos + (unsigned short)__popc(mm));
                __syncwarp();
            }
        }
        __syncthreads();
    }
}

// Per-segment: CDF in smem, binary-search bin per masked rank, integer Σb.
__global__ void __launch_bounds__(1024) binsum_kernel(
    const float* __restrict__ h0, const float* __restrict__ h1, const float* __restrict__ h2,
    const float* __restrict__ mn0, const float* __restrict__ mn1, const float* __restrict__ mn2,
    const float* __restrict__ mx0, const float* __restrict__ mx1, const float* __restrict__ mx2) {
    __shared__ float        cdf[256];
    __shared__ unsigned int ssum[32];
    int seg = blockIdx.x;
    int l = seg >> 8, c = seg & 255;
    const float* hist = ((l == 0) ? h0 : (l == 1) ? h1 : h2) + (size_t)c * kBins;
    int tid = threadIdx.x;
    if (tid == 0) {
        float run = 0.f;
        for (int j = 0; j < 256; j++) { run += hist[j]; cdf[j] = run; }
    }
    __syncthreads();
    float total = cdf[255];
    const unsigned int* keys = g_bufA + (size_t)seg * kHW; // 4 passes end in A
    unsigned int sumb = 0;
    for (int r = tid; r < kHW; r += 1024) {
        unsigned int k = keys[r];
        if (k & 1u) {
            // t_r = ((r+1)/N)*total in f32, matching the reference exactly
            float t = (float)(r + 1) * (1.0f / 65536.0f) * total;
            int lo = 0, hi = 256; // searchsorted(cdf, t, 'left')
            while (lo < hi) {
                int mid = (lo + hi) >> 1;
                if (cdf[mid] < t) lo = mid + 1; else hi = mid;
            }
            sumb += (unsigned int)min(lo, 255);
        }
    }
    int lane = tid & 31, warp = tid >> 5;
#pragma unroll
    for (int off = 16; off > 0; off >>= 1)
        sumb += __shfl_down_sync(0xFFFFFFFFu, sumb, off);
    if (lane == 0) ssum[warp] = sumb;
    __syncthreads();
    if (warp == 0) {
        unsigned int s = ssum[lane];
#pragma unroll
        for (int off = 16; off > 0; off >>= 1)
            s += __shfl_down_sync(0xFFFFFFFFu, s, off);
        if (lane == 0) {
            float lov = ((l == 0) ? mn0 : (l == 1) ? mn1 : mn2)[c];
            float hiv = ((l == 0) ? mx0 : (l == 1) ? mx1 : mx2)[c];
            // Σ_masked matched = M_c*lo + (hi-lo)/255 * Σb
            double contrib = (double)g_Mc[c] * (double)lov +
                             (double)(hiv - lov) * (1.0 / 255.0) * (double)s;
            atomicAdd(&g_S2[l], contrib);
        }
    }
}

__global__ void finalize_kernel(const float* __restrict__ w, float* __restrict__ out) {
    if (threadIdx.x == 0 && blockIdx.x == 0) {
        double cnt = 0.0;
        for (int c = 0; c < kC; c++) cnt += (double)g_Mc[c];
        double loss = 0.0;
        for (int l = 0; l < kL; l++)
            loss += (double)w[l] * ((g_S1[l] - g_S2[l]) / cnt);
        out[0] = (float)loss;
    }
}

extern "C" void kernel_launch(void* const* d_in, const int* in_sizes, int n_in,
                              void* d_out, int out_size) {
    (void)n_in; (void)out_size;
    // Detect input ordering:
    //  dict order:      opt0,hist0,minv0,maxv0, opt1,... , mip_weights, mask, bins
    //  signature order: opt0..2, hist0..2, minv0..2, maxv0..2, mip_weights, mask, bins
    int iopt[3], ihist[3], imin[3], imax[3];
    if (in_sizes[1] == kC * kBins) { // 65536 => dict (interleaved) order
        for (int l = 0; l < 3; l++) {
            iopt[l] = 4 * l; ihist[l] = 4 * l + 1; imin[l] = 4 * l + 2; imax[l] = 4 * l + 3;
        }
    } else { // signature order
        for (int l = 0; l < 3; l++) {
            iopt[l] = l; ihist[l] = 3 + l; imin[l] = 6 + l; imax[l] = 9 + l;
        }
    }
    const int iw = 12, imask = 13;

    const float* opt0 = (const float*)d_in[iopt[0]];
    const float* opt1 = (const float*)d_in[iopt[1]];
    const float* opt2 = (const float*)d_in[iopt[2]];
    const float* h0   = (const float*)d_in[ihist[0]];
    const float* h1   = (const float*)d_in[ihist[1]];
    const float* h2   = (const float*)d_in[ihist[2]];
    const float* mn0  = (const float*)d_in[imin[0]];
    const float* mn1  = (const float*)d_in[imin[1]];
    const float* mn2  = (const float*)d_in[imin[2]];
    const float* mx0  = (const float*)d_in[imax[0]];
    const float* mx1  = (const float*)d_in[imax[1]];
    const float* mx2  = (const float*)d_in[imax[2]];
    const float* w    = (const float*)d_in[iw];
    const int*   mask = (const int*)  d_in[imask];

    init_kernel<<<1, 256>>>();
    build_kernel<<<dim3(8, kSegs), 256>>>(opt0, opt1, opt2, mask);
    sort_kernel<<<kSegs, 1024>>>();
    binsum_kernel<<<kSegs, 1024>>>(h0, h1, h2, mn0, mn1, mn2, mx0, mx1, mx2);
    finalize_kernel<<<1, 32>>>(w, (float*)d_out);
}

// round 3
// speedup vs baseline: 1.0050x; 1.0050x over previous
#include <cuda_runtime.h>
#include <stdint.h>

// Problem constants
static const int kC    = 256;
static const int kHW   = 65536;   // H*W per channel
static const int kL    = 3;
static const int kSegs = 768;     // 3 levels * 256 channels
static const int kBins = 256;

// Scratch (device globals; no allocation allowed)
__device__ unsigned int g_bufA[(size_t)kSegs * kHW]; // 192 MB
__device__ unsigned int g_bufB[(size_t)kSegs * kHW]; // 192 MB
__device__ double       g_S1[kL];
__device__ double       g_S2[kL];
__device__ unsigned int g_Mc[kC];

// Order-preserving float->u32 transform, mask bit stuffed into LSB.
__device__ __forceinline__ unsigned int key_xform(float f, int m) {
    unsigned int u = __float_as_uint(f);
    u = (u & 0x80000000u) ? ~u : (u | 0x80000000u);
    return (u & ~1u) | (m != 0 ? 1u : 0u);
}

__global__ void init_kernel() {
    int t = threadIdx.x;
    if (t < kL) { g_S1[t] = 0.0; g_S2[t] = 0.0; }
    if (t < kC) g_Mc[t] = 0u;
}

// Build keys + masked sums. grid = (8, 768), 256 threads. 8192 elems/block.
__global__ void build_kernel(const float* __restrict__ opt0,
                             const float* __restrict__ opt1,
                             const float* __restrict__ opt2,
                             const int*  __restrict__ mask) {
    int seg = blockIdx.y;
    int l = seg >> 8;
    int c = seg & 255;
    const float* opt = (l == 0) ? opt0 : (l == 1) ? opt1 : opt2;
    const float4* optv = reinterpret_cast<const float4*>(opt) + (size_t)c * (kHW / 4);
    const int4*   mv   = reinterpret_cast<const int4*>(mask)  + (size_t)c * (kHW / 4);
    uint4* dstv = reinterpret_cast<uint4*>(g_bufA + (size_t)seg * kHW);

    int base = blockIdx.x * 2048; // in float4 units
    float fsum = 0.f;
    int   msum = 0;
#pragma unroll
    for (int i = 0; i < 8; i++) {
        int vi = base + i * 256 + threadIdx.x;
        float4 v = optv[vi];
        int4   m = mv[vi];
        uint4 k;
        k.x = key_xform(v.x, m.x);
        k.y = key_xform(v.y, m.y);
        k.z = key_xform(v.z, m.z);
        k.w = key_xform(v.w, m.w);
        dstv[vi] = k;
        if (m.x) { fsum += v.x; msum++; }
        if (m.y) { fsum += v.y; msum++; }
        if (m.z) { fsum += v.z; msum++; }
        if (m.w) { fsum += v.w; msum++; }
    }
    __shared__ float sf[8];
    __shared__ int   si[8];
    int lane = threadIdx.x & 31, warp = threadIdx.x >> 5;
#pragma unroll
    for (int off = 16; off > 0; off >>= 1) {
        fsum += __shfl_down_sync(0xFFFFFFFFu, fsum, off);
        msum += __shfl_down_sync(0xFFFFFFFFu, msum, off);
    }
    if (lane == 0) { sf[warp] = fsum; si[warp] = msum; }
    __syncthreads();
    if (warp == 0) {
        float f  = (lane < 8) ? sf[lane] : 0.f;
        int   mi = (lane < 8) ? si[lane] : 0;
#pragma unroll
        for (int off = 16; off > 0; off >>= 1) {
            f  += __shfl_down_sync(0xFFFFFFFFu, f,  off);
            mi += __shfl_down_sync(0xFFFFFFFFu, mi, off);
        }
        if (lane == 0) {
            atomicAdd(&g_S1[l], (double)f);
            if (l == 0) atomicAdd(&g_Mc[c], (unsigned int)mi);
        }
    }
}

// Per-segment 4-pass LSD radix sort (8-bit digits), one CTA per segment.
// Stable scatter: per-tile u16 histograms + match_any warp ranking.
__global__ void __launch_bounds__(1024, 2) sort_kernel() {
    __shared__ unsigned short tileHist[64 * 256]; // 32 KB, counts/positions fit u16
    __shared__ unsigned int   digitStart[256];

    int seg = blockIdx.x;
    unsigned int* A = g_bufA + (size_t)seg * kHW;
    unsigned int* B = g_bufB + (size_t)seg * kHW;
    int tid  = threadIdx.x;
    int warp = tid >> 5, lane = tid & 31;
    unsigned int lt_mask = (1u << lane) - 1u;

    for (int pass = 0; pass < 4; pass++) {
        int shift = pass * 8;
        unsigned int* src = (pass & 1) ? B : A;
        unsigned int* dst = (pass & 1) ? A : B;

        // zero tile histograms (32KB = 8192 u32 words)
        for (int i = tid; i < 8192; i += 1024)
            reinterpret_cast<unsigned int*>(tileHist)[i] = 0u;
        __syncthreads();

        // Phase A: per-tile digit histograms. Warp w owns tiles w and w+32.
        for (int t = warp; t < 64; t += 32) {
            unsigned short* h = tileHist + t * 256;
            int tb = t * 1024;
            for (int it = 0; it < 32; it++) {
                unsigned int key = src[tb + it * 32 + lane];
                unsigned int d = (key >> shift) & 255u;
                unsigned int mm = __match_any_sync(0xFFFFFFFFu, d);
                int leader = __ffs(mm) - 1;
                if (lane == leader)
                    h[d] = (unsigned short)(h[d] + (unsigned short)__popc(mm));
                __syncwarp();
            }
        }
        __syncthreads();

        // Per-digit exclusive prefix over tiles + digit totals
        if (tid < 256) {
            unsigned int run = 0;
            for (int t = 0; t < 64; t++) {
                unsigned int v = tileHist[t * 256 + tid];
                tileHist[t * 256 + tid] = (unsigned short)run;
                run += v;
            }
            digitStart[tid] = run; // temporarily: total count for this digit
        }
        __syncthreads();

        // Exclusive scan of 256 digit totals (one warp, 8 digits/lane)
        if (warp == 0) {
            unsigned int v[8], s = 0;
#pragma unroll
            for (int j = 0; j < 8; j++) { v[j] = digitStart[lane * 8 + j]; s += v[j]; }
            unsigned int incl = s;
#pragma unroll
            for (int off = 1; off < 32; off <<= 1) {
                unsigned int o = __shfl_up_sync(0xFFFFFFFFu, incl, off);
                if (lane >= off) incl += o;
            }
            unsigned int excl = incl - s;
#pragma unroll
            for (int j = 0; j < 8; j++) { digitStart[lane * 8 + j] = excl; excl += v[j]; }
        }
        __syncthreads();

        // Fold digit bases into tile prefixes -> absolute scatter bases
        if (tid < 256) {
            unsigned int ds = digitStart[tid];
            for (int t = 0; t < 64; t++)
                tileHist[t * 256 + tid] =
                    (unsigned short)(tileHist[t * 256 + tid] + ds);
        }
        __syncthreads();

        // Phase B: stable scatter
        for (int t = warp; t < 64; t += 32) {
            unsigned short* h = tileHist + t * 256;
            int tb = t * 1024;
            for (int it = 0; it < 32; it++) {
                unsigned int key = src[tb + it * 32 + lane];
                unsigned int d = (key >> shift) & 255u;
                unsigned int mm = __match_any_sync(0xFFFFFFFFu, d);
                int leader = __ffs(mm) - 1;
                unsigned int rank = __popc(mm & lt_mask);
                unsigned int basepos = h[d]; // all lanes read (broadcast/dup ok)
                dst[basepos + rank] = key;
                if (lane == leader)
                    h[d] = (unsigned short)(basepos + (unsigned short)__popc(mm));
                __syncwarp();
            }
        }
        __syncthreads();
    }
}

// Per-segment: CDF in smem, binary-search bin per masked rank, integer Σb.
__global__ void __launch_bounds__(1024) binsum_kernel(
    const float* __restrict__ h0, const float* __restrict__ h1, const float* __restrict__ h2,
    const float* __restrict__ mn0, const float* __restrict__ mn1, const float* __restrict__ mn2,
    const float* __restrict__ mx0, const float* __restrict__ mx1, const float* __restrict__ mx2) {
    __shared__ float        cdf[256];
    __shared__ unsigned int ssum[32];
    int seg = blockIdx.x;
    int l = seg >> 8, c = seg & 255;
    const float* hist = ((l == 0) ? h0 : (l == 1) ? h1 : h2) + (size_t)c * kBins;
    int tid = threadIdx.x;
    if (tid == 0) {
        float run = 0.f;
        for (int j = 0; j < 256; j++) { run += hist[j]; cdf[j] = run; }
    }
    __syncthreads();
    float total = cdf[255];
    const unsigned int* keys = g_bufA + (size_t)seg * kHW; // 4 passes end in A
    unsigned int sumb = 0;
    for (int r = tid; r < kHW; r += 1024) {
        unsigned int k = keys[r];
        if (k & 1u) {
            // t_r = ((r+1)/N)*total in f32, matching the reference exactly
            float t = (float)(r + 1) * (1.0f / 65536.0f) * total;
            int lo = 0, hi = 256; // searchsorted(cdf, t, 'left')
            while (lo < hi) {
                int mid = (lo + hi) >> 1;
                if (cdf[mid] < t) lo = mid + 1; else hi = mid;
            }
            sumb += (unsigned int)min(lo, 255);
        }
    }
    int lane = tid & 31, warp = tid >> 5;
#pragma unroll
    for (int off = 16; off > 0; off >>= 1)
        sumb += __shfl_down_sync(0xFFFFFFFFu, sumb, off);
    if (lane == 0) ssum[warp] = sumb;
    __syncthreads();
    if (warp == 0) {
        unsigned int s = ssum[lane];
#pragma unroll
        for (int off = 16; off > 0; off >>= 1)
            s += __shfl_down_sync(0xFFFFFFFFu, s, off);
        if (lane == 0) {
            float lov = ((l == 0) ? mn0 : (l == 1) ? mn1 : mn2)[c];
            float hiv = ((l == 0) ? mx0 : (l == 1) ? mx1 : mx2)[c];
            // Σ_masked matched = M_c*lo + (hi-lo)/255 * Σb
            double contrib = (double)g_Mc[c] * (double)lov +
                             (double)(hiv - lov) * (1.0 / 255.0) * (double)s;
            atomicAdd(&g_S2[l], contrib);
        }
    }
}

__global__ void finalize_kernel(const float* __restrict__ w, float* __restrict__ out) {
    if (threadIdx.x == 0 && blockIdx.x == 0) {
        double cnt = 0.0;
        for (int c = 0; c < kC; c++) cnt += (double)g_Mc[c];
        double loss = 0.0;
        for (int l = 0; l < kL; l++)
            loss += (double)w[l] * ((g_S1[l] - g_S2[l]) / cnt);
        out[0] = (float)loss;
    }
}

extern "C" void kernel_launch(void* const* d_in, const int* in_sizes, int n_in,
                              void* d_out, int out_size) {
    (void)n_in; (void)out_size;
    // Detect input ordering:
    //  dict order:      opt0,hist0,minv0,maxv0, opt1,... , mip_weights, mask, bins
    //  signature order: opt0..2, hist0..2, minv0..2, maxv0..2, mip_weights, mask, bins
    int iopt[3], ihist[3], imin[3], imax[3];
    if (in_sizes[1] == kC * kBins) { // 65536 => dict (interleaved) order
        for (int l = 0; l < 3; l++) {
            iopt[l] = 4 * l; ihist[l] = 4 * l + 1; imin[l] = 4 * l + 2; imax[l] = 4 * l + 3;
        }
    } else { // signature order
        for (int l = 0; l < 3; l++) {
            iopt[l] = l; ihist[l] = 3 + l; imin[l] = 6 + l; imax[l] = 9 + l;
        }
    }
    const int iw = 12, imask = 13;

    const float* opt0 = (const float*)d_in[iopt[0]];
    const float* opt1 = (const float*)d_in[iopt[1]];
    const float* opt2 = (const float*)d_in[iopt[2]];
    const float* h0   = (const float*)d_in[ihist[0]];
    const float* h1   = (const float*)d_in[ihist[1]];
    const float* h2   = (const float*)d_in[ihist[2]];
    const float* mn0  = (const float*)d_in[imin[0]];
    const float* mn1  = (const float*)d_in[imin[1]];
    const float* mn2  = (const float*)d_in[imin[2]];
    const float* mx0  = (const float*)d_in[imax[0]];
    const float* mx1  = (const float*)d_in[imax[1]];
    const float* mx2  = (const float*)d_in[imax[2]];
    const float* w    = (const float*)d_in[iw];
    const int*   mask = (const int*)  d_in[imask];

    init_kernel<<<1, 256>>>();
    build_kernel<<<dim3(8, kSegs), 256>>>(opt0, opt1, opt2, mask);
    sort_kernel<<<kSegs, 1024>>>();
    binsum_kernel<<<kSegs, 1024>>>(h0, h1, h2, mn0, mn1, mn2, mx0, mx1, mx2);
    finalize_kernel<<<1, 32>>>(w, (float*)d_out);
}

// round 4
// speedup vs baseline: 17.7973x; 17.7082x over previous
#include <cuda_runtime.h>
#include <stdint.h>

static const int kC = 256, kHW = 65536, kBins = 256;
static const int kB = 16384;               // value buckets (top-14 key bits)

__device__ double       g_S1[3];
__device__ double       g_S2[3];
__device__ unsigned int g_Mc[kC];

__device__ __forceinline__ unsigned int key_xform(float f) {
    unsigned int u = __float_as_uint(f);
    return (u & 0x80000000u) ? ~u : (u | 0x80000000u);
}

// reference-exact f32 quantile target: t_r = ((float)r / 65536) * total
__device__ __forceinline__ float t_of(int r, float total) {
    float fr = (float)r * 0x1p-16f;        // exact (power of two)
    return fr * total;                     // single f32 RN mul, as in reference
}

__global__ void init_kernel() {
    if (threadIdx.x < 3) { g_S1[threadIdx.x] = 0.0; g_S2[threadIdx.x] = 0.0; }
}

__global__ void __launch_bounds__(1024) fused_kernel(
    const float* __restrict__ o0, const float* __restrict__ o1, const float* __restrict__ o2,
    const float* __restrict__ h0, const float* __restrict__ h1, const float* __restrict__ h2,
    const float* __restrict__ mn0, const float* __restrict__ mn1, const float* __restrict__ mn2,
    const float* __restrict__ mx0, const float* __restrict__ mx1, const float* __restrict__ mx2,
    const int* __restrict__ mask) {
    extern __shared__ unsigned int dyn[];
    unsigned int* H = dyn;                 // packed: tot | masked<<16
    unsigned int* T = dyn + kB;            // inclusive scan of totals
    unsigned int* M = dyn + 2 * kB;        // inclusive scan of masked
    __shared__ float        cdf[256];
    __shared__ float        swf[32];
    __shared__ unsigned int swu[32], swu2[32];
    __shared__ double       swd[32];
    __shared__ unsigned int sMc;
    __shared__ float        sTotal;

    int bid = blockIdx.x;
    int c = bid / 3, l = bid % 3;          // 3 levels of a channel adjacent -> mask L2 reuse
    const float* opt = (l == 0) ? o0 : (l == 1) ? o1 : o2;
    int tid = threadIdx.x, lane = tid & 31, warp = tid >> 5;

    for (int i = tid; i < kB; i += 1024) H[i] = 0u;
    __syncthreads();

    // ---- histogram + masked sum ----
    const float4* ov = reinterpret_cast<const float4*>(opt) + (size_t)c * (kHW / 4);
    const int4*   mv = reinterpret_cast<const int4*>(mask)  + (size_t)c * (kHW / 4);
    float fsum = 0.f; unsigned int msum = 0u;
#pragma unroll 4
    for (int i = 0; i < 16; i++) {
        float4 v = ov[tid + 1024 * i];
        int4   m = mv[tid + 1024 * i];
        atomicAdd(&H[key_xform(v.x) >> 18], 1u + (m.x ? 0x10000u : 0u));
        atomicAdd(&H[key_xform(v.y) >> 18], 1u + (m.y ? 0x10000u : 0u));
        atomicAdd(&H[key_xform(v.z) >> 18], 1u + (m.z ? 0x10000u : 0u));
        atomicAdd(&H[key_xform(v.w) >> 18], 1u + (m.w ? 0x10000u : 0u));
        if (m.x) { fsum += v.x; msum++; }
        if (m.y) { fsum += v.y; msum++; }
        if (m.z) { fsum += v.z; msum++; }
        if (m.w) { fsum += v.w; msum++; }
    }
#pragma unroll
    for (int off = 16; off > 0; off >>= 1) {
        fsum += __shfl_down_sync(0xFFFFFFFFu, fsum, off);
        msum += __shfl_down_sync(0xFFFFFFFFu, msum, off);
    }
    if (lane == 0) { swf[warp] = fsum; swu[warp] = msum; }
    __syncthreads();
    if (warp == 0) {
        float f = swf[lane]; unsigned int mi = swu[lane];
#pragma unroll
        for (int off = 16; off > 0; off >>= 1) {
            f  += __shfl_down_sync(0xFFFFFFFFu, f, off);
            mi += __shfl_down_sync(0xFFFFFFFFu, mi, off);
        }
        if (lane == 0) {
            sMc = mi;
            atomicAdd(&g_S1[l], (double)f);
            if (l == 0) g_Mc[c] = mi;
        }
    }
    __syncthreads();

    // ---- inclusive scans of totals / masked over 16384 buckets ----
    unsigned int runT = 0, runM = 0;
    int base = tid * 16;
#pragma unroll
    for (int i = 0; i < 16; i++) {
        unsigned int h = H[base + i];
        runT += h & 0xFFFFu; runM += h >> 16;
        T[base + i] = runT;  M[base + i] = runM;
    }
    unsigned int iT = runT, iM = runM;
#pragma unroll
    for (int off = 1; off < 32; off <<= 1) {
        unsigned int a = __shfl_up_sync(0xFFFFFFFFu, iT, off);
        unsigned int b = __shfl_up_sync(0xFFFFFFFFu, iM, off);
        if (lane >= off) { iT += a; iM += b; }
    }
    if (lane == 31) { swu[warp] = iT; swu2[warp] = iM; }
    __syncthreads();
    if (warp == 0) {
        unsigned int a = swu[lane], b = swu2[lane];
#pragma unroll
        for (int off = 1; off < 32; off <<= 1) {
            unsigned int x = __shfl_up_sync(0xFFFFFFFFu, a, off);
            unsigned int y = __shfl_up_sync(0xFFFFFFFFu, b, off);
            if (lane >= off) { a += x; b += y; }
        }
        swu[lane] = a; swu2[lane] = b;
    }
    __syncthreads();
    unsigned int offT = (warp ? swu[warp - 1] : 0u) + iT - runT;
    unsigned int offM = (warp ? swu2[warp - 1] : 0u) + iM - runM;
#pragma unroll
    for (int i = 0; i < 16; i++) { T[base + i] += offT; M[base + i] += offM; }

    // ---- target-histogram CDF (serial f32, reference rounding) ----
    const float* hist = ((l == 0) ? h0 : (l == 1) ? h1 : h2) + (size_t)c * kBins;
    if (tid == 0) {
        float run = 0.f;
        for (int j = 0; j < 256; j++) { run += hist[j]; cdf[j] = run; }
        sTotal = run;
    }
    __syncthreads();

    // ---- 255 bin boundaries: rank threshold + masked-prefix lookup ----
    double contrib = 0.0;
    if (tid < 255) {
        float cj = cdf[tid], total = sTotal;
        if (t_of(65536, total) > cj) {
            int lo = 1, hi = 65536;                  // min r with t_r > cdf[j]
            while (lo < hi) { int mid = (lo + hi) >> 1;
                              if (t_of(mid, total) > cj) hi = mid; else lo = mid + 1; }
            unsigned int s1 = (unsigned int)(lo - 1); // CM argument
            double cm = 0.0;
            if (s1 > 0) {
                int blo = 0, bhi = kB - 1;           // min B with T[B] >= s1
                while (blo < bhi) { int bm = (blo + bhi) >> 1;
                                    if (T[bm] >= s1) bhi = bm; else blo = bm + 1; }
                unsigned int pT = blo ? T[blo - 1] : 0u, pM = blo ? M[blo - 1] : 0u;
                unsigned int nB = T[blo] - pT, mB = M[blo] - pM;
                unsigned int mm = s1 - pT;
                cm = (double)pM + (nB ? (double)mB * (double)mm / (double)nB : 0.0);
            }
            contrib = (double)sMc - cm;
        }
    }
#pragma unroll
    for (int off = 16; off > 0; off >>= 1)
        contrib += __shfl_down_sync(0xFFFFFFFFu, contrib, off);
    if (lane == 0) swd[warp] = contrib;
    __syncthreads();
    if (warp == 0) {
        double d = swd[lane];
#pragma unroll
        for (int off = 16; off > 0; off >>= 1)
            d += __shfl_down_sync(0xFFFFFFFFu, d, off);
        if (lane == 0) {
            float lov = ((l == 0) ? mn0 : (l == 1) ? mn1 : mn2)[c];
            float hiv = ((l == 0) ? mx0 : (l == 1) ? mx1 : mx2)[c];
            double S2seg = (double)sMc * (double)lov +
                           (double)(hiv - lov) * (1.0 / 255.0) * d;
            atomicAdd(&g_S2[l], S2seg);
        }
    }
}

__global__ void finalize_kernel(const float* __restrict__ w, float* __restrict__ out) {
    if (threadIdx.x == 0 && blockIdx.x == 0) {
        double cnt = 0.0;
        for (int c = 0; c < kC; c++) cnt += (double)g_Mc[c];
        double loss = 0.0;
        for (int l = 0; l < 3; l++)
            loss += (double)w[l] * ((g_S1[l] - g_S2[l]) / cnt);
        out[0] = (float)loss;
    }
}

extern "C" void kernel_launch(void* const* d_in, const int* in_sizes, int n_in,
                              void* d_out, int out_size) {
    (void)n_in; (void)out_size;
    int iopt[3], ihist[3], imin[3], imax[3];
    if (in_sizes[1] == kC * kBins) {       // dict (interleaved) order
        for (int l = 0; l < 3; l++) { iopt[l] = 4*l; ihist[l] = 4*l+1; imin[l] = 4*l+2; imax[l] = 4*l+3; }
    } else {                               // signature order
        for (int l = 0; l < 3; l++) { iopt[l] = l; ihist[l] = 3+l; imin[l] = 6+l; imax[l] = 9+l; }
    }
    const int iw = 12, imask = 13;

    static int smem_set = 0;
    if (!smem_set) {
        cudaFuncSetAttribute(fused_kernel, cudaFuncAttributeMaxDynamicSharedMemorySize,
                             3 * kB * sizeof(unsigned int));
        smem_set = 1;
    }

    init_kernel<<<1, 32>>>();
    fused_kernel<<<768, 1024, 3 * kB * sizeof(unsigned int)>>>(
        (const float*)d_in[iopt[0]], (const float*)d_in[iopt[1]], (const float*)d_in[iopt[2]],
        (const float*)d_in[ihist[0]], (const float*)d_in[ihist[1]], (const float*)d_in[ihist[2]],
        (const float*)d_in[imin[0]], (const float*)d_in[imin[1]], (const float*)d_in[imin[2]],
        (const float*)d_in[imax[0]], (const float*)d_in[imax[1]], (const float*)d_in[imax[2]],
        (const int*)d_in[imask]);
    finalize_kernel<<<1, 32>>>((const float*)d_in[iw], (float*)d_out);
}

// round 5
// speedup vs baseline: 28.1083x; 1.5794x over previous
#include <cuda_runtime.h>
#include <stdint.h>

static const int kC = 256, kHW = 65536, kBins = 256;
static const int kB = 8192;                // value buckets (top-13 key bits)
static const int kSegs = 768;

__device__ double       g_pS1[kSegs];
__device__ double       g_pS2[kSegs];
__device__ unsigned int g_Mc[kC];
__device__ unsigned int g_done;            // zero at load; reset by last block

__device__ __forceinline__ unsigned int key_xform(float f) {
    unsigned int u = __float_as_uint(f);
    return (u & 0x80000000u) ? ~u : (u | 0x80000000u);
}

// reference-exact f32 quantile target: t_r = ((float)r * 2^-16) * total
__device__ __forceinline__ float t_of(int r, float total) {
    return ((float)r * 0x1p-16f) * total;
}

__global__ void __launch_bounds__(1024) fused_kernel(
    const float* __restrict__ o0, const float* __restrict__ o1, const float* __restrict__ o2,
    const float* __restrict__ h0, const float* __restrict__ h1, const float* __restrict__ h2,
    const float* __restrict__ mn0, const float* __restrict__ mn1, const float* __restrict__ mn2,
    const float* __restrict__ mx0, const float* __restrict__ mx1, const float* __restrict__ mx2,
    const int* __restrict__ mask, const float* __restrict__ w, float* __restrict__ out) {
    extern __shared__ unsigned int dyn[];
    unsigned int* H = dyn;                 // packed: tot | masked<<16
    unsigned int* T = dyn + kB;            // inclusive scan of totals
    unsigned int* M = dyn + 2 * kB;        // inclusive scan of masked
    __shared__ float        cdf[256];
    __shared__ float        swf[32];
    __shared__ unsigned int swu[32], swu2[32];
    __shared__ double       swd[32];
    __shared__ unsigned int sMc, sticket;
    __shared__ float        sTotal;

    int bid = blockIdx.x;
    int c = bid / 3, l = bid % 3;          // 3 levels of a channel adjacent -> mask L2 reuse
    const float* opt = (l == 0) ? o0 : (l == 1) ? o1 : o2;
    int tid = threadIdx.x, lane = tid & 31, warp = tid >> 5;

    for (int i = tid; i < kB; i += 1024) H[i] = 0u;
    __syncthreads();

    // ---- histogram + masked sum ----
    const float4* ov = reinterpret_cast<const float4*>(opt) + (size_t)c * (kHW / 4);
    const int4*   mv = reinterpret_cast<const int4*>(mask)  + (size_t)c * (kHW / 4);
    float fsum = 0.f; unsigned int msum = 0u;
#pragma unroll 4
    for (int i = 0; i < 16; i++) {
        float4 v = __ldcs(&ov[tid + 1024 * i]);   // streaming: no L2 pollution
        int4   m = mv[tid + 1024 * i];            // default: mask reused by 3 CTAs
        atomicAdd(&H[key_xform(v.x) >> 19], 1u + (m.x ? 0x10000u : 0u));
        atomicAdd(&H[key_xform(v.y) >> 19], 1u + (m.y ? 0x10000u : 0u));
        atomicAdd(&H[key_xform(v.z) >> 19], 1u + (m.z ? 0x10000u : 0u));
        atomicAdd(&H[key_xform(v.w) >> 19], 1u + (m.w ? 0x10000u : 0u));
        if (m.x) { fsum += v.x; msum++; }
        if (m.y) { fsum += v.y; msum++; }
        if (m.z) { fsum += v.z; msum++; }
        if (m.w) { fsum += v.w; msum++; }
    }
#pragma unroll
    for (int off = 16; off > 0; off >>= 1) {
        fsum += __shfl_down_sync(0xFFFFFFFFu, fsum, off);
        msum += __shfl_down_sync(0xFFFFFFFFu, msum, off);
    }
    if (lane == 0) { swf[warp] = fsum; swu[warp] = msum; }
    __syncthreads();
    if (warp == 0) {
        float f = swf[lane]; unsigned int mi = swu[lane];
#pragma unroll
        for (int off = 16; off > 0; off >>= 1) {
            f  += __shfl_down_sync(0xFFFFFFFFu, f, off);
            mi += __shfl_down_sync(0xFFFFFFFFu, mi, off);
        }
        if (lane == 0) {
            sMc = mi;
            g_pS1[bid] = (double)f;
            if (l == 0) g_Mc[c] = mi;
        }
    }
    __syncthreads();

    // ---- inclusive scans of totals / masked over kB buckets ----
    unsigned int runT = 0, runM = 0;
    int base = tid * 8;
#pragma unroll
    for (int i = 0; i < 8; i++) {
        unsigned int h = H[base + i];
        runT += h & 0xFFFFu; runM += h >> 16;
        T[base + i] = runT;  M[base + i] = runM;
    }
    unsigned int iT = runT, iM = runM;
#pragma unroll
    for (int off = 1; off < 32; off <<= 1) {
        unsigned int a = __shfl_up_sync(0xFFFFFFFFu, iT, off);
        unsigned int b = __shfl_up_sync(0xFFFFFFFFu, iM, off);
        if (lane >= off) { iT += a; iM += b; }
    }
    if (lane == 31) { swu[warp] = iT; swu2[warp] = iM; }
    __syncthreads();
    if (warp == 0) {
        unsigned int a = swu[lane], b = swu2[lane];
#pragma unroll
        for (int off = 1; off < 32; off <<= 1) {
            unsigned int x = __shfl_up_sync(0xFFFFFFFFu, a, off);
            unsigned int y = __shfl_up_sync(0xFFFFFFFFu, b, off);
            if (lane >= off) { a += x; b += y; }
        }
        swu[lane] = a; swu2[lane] = b;
    }
    __syncthreads();
    unsigned int offT = (warp ? swu[warp - 1] : 0u) + iT - runT;
    unsigned int offM = (warp ? swu2[warp - 1] : 0u) + iM - runM;
#pragma unroll
    for (int i = 0; i < 8; i++) { T[base + i] += offT; M[base + i] += offM; }

    // ---- target-histogram CDF (serial f32, reference rounding) ----
    const float* hist = ((l == 0) ? h0 : (l == 1) ? h1 : h2) + (size_t)c * kBins;
    if (tid == 0) {
        float run = 0.f;
        for (int j = 0; j < 256; j++) { run += hist[j]; cdf[j] = run; }
        sTotal = run;
    }
    __syncthreads();

    // ---- 255 bin boundaries: rank threshold + masked-prefix lookup ----
    double contrib = 0.0;
    if (tid < 255) {
        float cj = cdf[tid], total = sTotal;
        if (t_of(65536, total) > cj) {
            int lo = 1, hi = 65536;                  // min r with t_r > cdf[j]
            while (lo < hi) { int mid = (lo + hi) >> 1;
                              if (t_of(mid, total) > cj) hi = mid; else lo = mid + 1; }
            unsigned int s1 = (unsigned int)(lo - 1);
            double cm = 0.0;
            if (s1 > 0) {
                int blo = 0, bhi = kB - 1;           // min B with T[B] >= s1
                while (blo < bhi) { int bm = (blo + bhi) >> 1;
                                    if (T[bm] >= s1) bhi = bm; else blo = bm + 1; }
                unsigned int pT = blo ? T[blo - 1] : 0u, pM = blo ? M[blo - 1] : 0u;
                unsigned int nB = T[blo] - pT, mB = M[blo] - pM;
                unsigned int mm = s1 - pT;
                cm = (double)pM + (nB ? (double)mB * (double)mm / (double)nB : 0.0);
            }
            contrib = (double)sMc - cm;
        }
    }
#pragma unroll
    for (int off = 16; off > 0; off >>= 1)
        contrib += __shfl_down_sync(0xFFFFFFFFu, contrib, off);
    if (lane == 0) swd[warp] = contrib;
    __syncthreads();
    if (warp == 0) {
        double d = swd[lane];
#pragma unroll
        for (int off = 16; off > 0; off >>= 1)
            d += __shfl_down_sync(0xFFFFFFFFu, d, off);
        if (lane == 0) {
            float lov = ((l == 0) ? mn0 : (l == 1) ? mn1 : mn2)[c];
            float hiv = ((l == 0) ? mx0 : (l == 1) ? mx1 : mx2)[c];
            g_pS2[bid] = (double)sMc * (double)lov +
                         (double)(hiv - lov) * (1.0 / 255.0) * d;
        }
    }

    // ---- last-arriving CTA folds the 768 partials into the scalar loss ----
    __syncthreads();
    if (tid == 0) {
        __threadfence();                       // publish g_pS1/g_pS2/g_Mc
        sticket = atomicAdd(&g_done, 1u);
    }
    __syncthreads();
    if (sticket == (unsigned int)(kSegs - 1) && warp == 0) {
        __threadfence();                       // acquire all partials
        double a0 = 0, a1 = 0, a2 = 0, b0 = 0, b1 = 0, b2 = 0, cnt = 0;
        for (int s = lane; s < kSegs; s += 32) {
            int ll = s % 3;
            double v1 = g_pS1[s], v2 = g_pS2[s];
            if (ll == 0)      { a0 += v1; b0 += v2; }
            else if (ll == 1) { a1 += v1; b1 += v2; }
            else              { a2 += v1; b2 += v2; }
        }
        for (int cc = lane; cc < kC; cc += 32) cnt += (double)g_Mc[cc];
#pragma unroll
        for (int off = 16; off > 0; off >>= 1) {
            a0 += __shfl_down_sync(0xFFFFFFFFu, a0, off);
            a1 += __shfl_down_sync(0xFFFFFFFFu, a1, off);
            a2 += __shfl_down_sync(0xFFFFFFFFu, a2, off);
            b0 += __shfl_down_sync(0xFFFFFFFFu, b0, off);
            b1 += __shfl_down_sync(0xFFFFFFFFu, b1, off);
            b2 += __shfl_down_sync(0xFFFFFFFFu, b2, off);
            cnt += __shfl_down_sync(0xFFFFFFFFu, cnt, off);
        }
        if (lane == 0) {
            double loss = (double)w[0] * ((a0 - b0) / cnt) +
                          (double)w[1] * ((a1 - b1) / cnt) +
                          (double)w[2] * ((a2 - b2) / cnt);
            out[0] = (float)loss;
            g_done = 0u;                      // reset for next graph replay
        }
    }
}

extern "C" void kernel_launch(void* const* d_in, const int* in_sizes, int n_in,
                              void* d_out, int out_size) {
    (void)n_in; (void)out_size;
    int iopt[3], ihist[3], imin[3], imax[3];
    if (in_sizes[1] == kC * kBins) {       // dict (interleaved) order
        for (int l = 0; l < 3; l++) { iopt[l] = 4*l; ihist[l] = 4*l+1; imin[l] = 4*l+2; imax[l] = 4*l+3; }
    } else {                               // signature order
        for (int l = 0; l < 3; l++) { iopt[l] = l; ihist[l] = 3+l; imin[l] = 6+l; imax[l] = 9+l; }
    }
    const int iw = 12, imask = 13;

    static int smem_set = 0;
    if (!smem_set) {
        cudaFuncSetAttribute(fused_kernel, cudaFuncAttributeMaxDynamicSharedMemorySize,
                             3 * kB * sizeof(unsigned int));
        smem_set = 1;
    }

    fused_kernel<<<kSegs, 1024, 3 * kB * sizeof(unsigned int)>>>(
        (const float*)d_in[iopt[0]], (const float*)d_in[iopt[1]], (const float*)d_in[iopt[2]],
        (const float*)d_in[ihist[0]], (const float*)d_in[ihist[1]], (const float*)d_in[ihist[2]],
        (const float*)d_in[imin[0]], (const float*)d_in[imin[1]], (const float*)d_in[imin[2]],
        (const float*)d_in[imax[0]], (const float*)d_in[imax[1]], (const float*)d_in[imax[2]],
        (const int*)d_in[imask], (const float*)d_in[iw], (float*)d_out);
}

// round 7
// speedup vs baseline: 31.8007x; 1.1314x over previous
#include <cuda_runtime.h>
#include <stdint.h>

static const int kC = 256, kHW = 65536, kBins = 256;
static const int kB = 8192;                // value buckets (top-13 key bits)
static const int kSegs = 768;
static const unsigned int kSent = 0xFFFFFFFFu;

__device__ double       g_pS1[kSegs];
__device__ double       g_pS2[kSegs];
__device__ unsigned int g_Mc[kC];
__device__ unsigned int g_done;            // zero at load; reset by last block

__device__ __forceinline__ unsigned int key_xform(float f) {
    unsigned int u = __float_as_uint(f);
    return (u & 0x80000000u) ? ~u : (u | 0x80000000u);
}

// f32 quantile target: t_r = ((float)r * 2^-16) * total  (monotone in r)
__device__ __forceinline__ float t_of(int r, float total) {
    return ((float)r * 0x1p-16f) * total;
}

__global__ void __launch_bounds__(1024, 2) fused_kernel(
    const float* __restrict__ o0, const float* __restrict__ o1, const float* __restrict__ o2,
    const float* __restrict__ h0, const float* __restrict__ h1, const float* __restrict__ h2,
    const float* __restrict__ mn0, const float* __restrict__ mn1, const float* __restrict__ mn2,
    const float* __restrict__ mx0, const float* __restrict__ mx1, const float* __restrict__ mx2,
    const int* __restrict__ mask, const float* __restrict__ w, float* __restrict__ out) {
    extern __shared__ unsigned int dyn[];
    unsigned int* H = dyn;                 // packed: tot | masked<<16
    unsigned int* T = dyn + kB;            // inclusive scan of totals
    unsigned int* M = dyn + 2 * kB;        // inclusive scan of masked
    __shared__ float        cdf[256];
    __shared__ unsigned int s1arr[256];    // boundary ranks (kSent = no contribution)
    __shared__ float        swf[32];
    __shared__ unsigned int swu[32], swu2[32];
    __shared__ double       swd[32];
    __shared__ unsigned int sMc, sticket;
    __shared__ float        sTotal;

    int bid = blockIdx.x;
    int c = bid / 3, l = bid % 3;          // 3 levels of a channel adjacent -> mask L2 reuse
    const float* opt = (l == 0) ? o0 : (l == 1) ? o1 : o2;
    int tid = threadIdx.x, lane = tid & 31, warp = tid >> 5;

    for (int i = tid; i < kB; i += 1024) H[i] = 0u;

    // ---- parallel target-CDF build (warp 0): 8 bins/lane + shuffle scan ----
    const float* hist = ((l == 0) ? h0 : (l == 1) ? h1 : h2) + (size_t)c * kBins;
    if (warp == 0) {
        const float4* hv = reinterpret_cast<const float4*>(hist);
        float4 a = hv[lane * 2], b = hv[lane * 2 + 1];
        float v[8] = {a.x, a.y, a.z, a.w, b.x, b.y, b.z, b.w};
        float run = 0.f, pref[8];
#pragma unroll
        for (int i = 0; i < 8; i++) { run += v[i]; pref[i] = run; }
        float incl = run;
#pragma unroll
        for (int off = 1; off < 32; off <<= 1) {
            float o = __shfl_up_sync(0xFFFFFFFFu, incl, off);
            if (lane >= off) incl += o;
        }
        float excl = incl - run;
#pragma unroll
        for (int i = 0; i < 8; i++) cdf[lane * 8 + i] = excl + pref[i];
        if (lane == 31) sTotal = incl;
    }
    __syncthreads();   // H zeroed, cdf + sTotal ready

    // ---- boundary ranks (overlaps with histogram start on other warps) ----
    if (tid < 255) {
        float cj = cdf[tid], total = sTotal;
        unsigned int s1 = kSent;
        if (t_of(65536, total) > cj) {
            int lo = 1, hi = 65536;                  // min r with t_r > cj
            while (lo < hi) { int mid = (lo + hi) >> 1;
                              if (t_of(mid, total) > cj) hi = mid; else lo = mid + 1; }
            s1 = (unsigned int)(lo - 1);
        }
        s1arr[tid] = s1;
    }

    // ---- histogram + masked sum ----
    const float4* ov = reinterpret_cast<const float4*>(opt) + (size_t)c * (kHW / 4);
    const int4*   mv = reinterpret_cast<const int4*>(mask)  + (size_t)c * (kHW / 4);
    float fsum = 0.f; unsigned int msum = 0u;
#pragma unroll 4
    for (int i = 0; i < 16; i++) {
        float4 v = __ldcs(&ov[tid + 1024 * i]);   // streaming: no L2 pollution
        int4   m = mv[tid + 1024 * i];            // mask reused by 3 CTAs via L2
        atomicAdd(&H[key_xform(v.x) >> 19], 1u + (m.x ? 0x10000u : 0u));
        atomicAdd(&H[key_xform(v.y) >> 19], 1u + (m.y ? 0x10000u : 0u));
        atomicAdd(&H[key_xform(v.z) >> 19], 1u + (m.z ? 0x10000u : 0u));
        atomicAdd(&H[key_xform(v.w) >> 19], 1u + (m.w ? 0x10000u : 0u));
        if (m.x) { fsum += v.x; msum++; }
        if (m.y) { fsum += v.y; msum++; }
        if (m.z) { fsum += v.z; msum++; }
        if (m.w) { fsum += v.w; msum++; }
    }
#pragma unroll
    for (int off = 16; off > 0; off >>= 1) {
        fsum += __shfl_down_sync(0xFFFFFFFFu, fsum, off);
        msum += __shfl_down_sync(0xFFFFFFFFu, msum, off);
    }
    if (lane == 0) { swf[warp] = fsum; swu[warp] = msum; }
    __syncthreads();
    if (warp == 0) {
        float f = swf[lane]; unsigned int mi = swu[lane];
#pragma unroll
        for (int off = 16; off > 0; off >>= 1) {
            f  += __shfl_down_sync(0xFFFFFFFFu, f, off);
            mi += __shfl_down_sync(0xFFFFFFFFu, mi, off);
        }
        if (lane == 0) {
            sMc = mi;
            g_pS1[bid] = (double)f;
            if (l == 0) g_Mc[c] = mi;
        }
    }
    __syncthreads();

    // ---- inclusive scans of totals / masked over kB buckets ----
    unsigned int runT = 0, runM = 0;
    int base = tid * 8;
#pragma unroll
    for (int i = 0; i < 8; i++) {
        unsigned int h = H[base + i];
        runT += h & 0xFFFFu; runM += h >> 16;
        T[base + i] = runT;  M[base + i] = runM;
    }
    unsigned int iT = runT, iM = runM;
#pragma unroll
    for (int off = 1; off < 32; off <<= 1) {
        unsigned int a = __shfl_up_sync(0xFFFFFFFFu, iT, off);
        unsigned int b = __shfl_up_sync(0xFFFFFFFFu, iM, off);
        if (lane >= off) { iT += a; iM += b; }
    }
    if (lane == 31) { swu[warp] = iT; swu2[warp] = iM; }
    __syncthreads();
    if (warp == 0) {
        unsigned int a = swu[lane], b = swu2[lane];
#pragma unroll
        for (int off = 1; off < 32; off <<= 1) {
            unsigned int x = __shfl_up_sync(0xFFFFFFFFu, a, off);
            unsigned int y = __shfl_up_sync(0xFFFFFFFFu, b, off);
            if (lane >= off) { a += x; b += y; }
        }
        swu[lane] = a; swu2[lane] = b;
    }
    __syncthreads();
    unsigned int offT = (warp ? swu[warp - 1] : 0u) + iT - runT;
    unsigned int offM = (warp ? swu2[warp - 1] : 0u) + iM - runM;
#pragma unroll
    for (int i = 0; i < 8; i++) { T[base + i] += offT; M[base + i] += offM; }
    __syncthreads();

    // ---- 255 boundaries: precomputed rank -> masked-prefix lookup ----
    double contrib = 0.0;
    if (tid < 255) {
        unsigned int s1 = s1arr[tid];
        if (s1 != kSent) {
            double cm = 0.0;
            if (s1 > 0) {
                int blo = 0, bhi = kB - 1;           // min B with T[B] >= s1
                while (blo < bhi) { int bm = (blo + bhi) >> 1;
                                    if (T[bm] >= s1) bhi = bm; else blo = bm + 1; }
                unsigned int pT = blo ? T[blo - 1] : 0u, pM = blo ? M[blo - 1] : 0u;
                unsigned int nB = T[blo] - pT, mB = M[blo] - pM;
                unsigned int mm = s1 - pT;
                cm = (double)pM + (nB ? (double)mB * (double)mm / (double)nB : 0.0);
            }
            contrib = (double)sMc - cm;
        }
    }
#pragma unroll
    for (int off = 16; off > 0; off >>= 1)
        contrib += __shfl_down_sync(0xFFFFFFFFu, contrib, off);
    if (lane == 0) swd[warp] = contrib;
    __syncthreads();
    if (warp == 0) {
        double d = swd[lane];
#pragma unroll
        for (int off = 16; off > 0; off >>= 1)
            d += __shfl_down_sync(0xFFFFFFFFu, d, off);
        if (lane == 0) {
            float lov = ((l == 0) ? mn0 : (l == 1) ? mn1 : mn2)[c];
            float hiv = ((l == 0) ? mx0 : (l == 1) ? mx1 : mx2)[c];
            g_pS2[bid] = (double)sMc * (double)lov +
                         (double)(hiv - lov) * (1.0 / 255.0) * d;
        }
    }

    // ---- last-arriving CTA folds the 768 partials into the scalar loss ----
    __syncthreads();
    if (tid == 0) {
        __threadfence();                       // publish g_pS1/g_pS2/g_Mc
        sticket = atomicAdd(&g_done, 1u);
    }
    __syncthreads();
    if (sticket == (unsigned int)(kSegs - 1) && warp == 0) {
        __threadfence();                       // acquire all partials
        double a0 = 0, a1 = 0, a2 = 0, b0 = 0, b1 = 0, b2 = 0, cnt = 0;
        for (int s = lane; s < kSegs; s += 32) {
            int ll = s % 3;
            double v1 = g_pS1[s], v2 = g_pS2[s];
            if (ll == 0)      { a0 += v1; b0 += v2; }
            else if (ll == 1) { a1 += v1; b1 += v2; }
            else              { a2 += v1; b2 += v2; }
        }
        for (int cc = lane; cc < kC; cc += 32) cnt += (double)g_Mc[cc];
#pragma unroll
        for (int off = 16; off > 0; off >>= 1) {
            a0 += __shfl_down_sync(0xFFFFFFFFu, a0, off);
            a1 += __shfl_down_sync(0xFFFFFFFFu, a1, off);
            a2 += __shfl_down_sync(0xFFFFFFFFu, a2, off);
            b0 += __shfl_down_sync(0xFFFFFFFFu, b0, off);
            b1 += __shfl_down_sync(0xFFFFFFFFu, b1, off);
            b2 += __shfl_down_sync(0xFFFFFFFFu, b2, off);
            cnt += __shfl_down_sync(0xFFFFFFFFu, cnt, off);
        }
        if (lane == 0) {
            double loss = (double)w[0] * ((a0 - b0) / cnt) +
                          (double)w[1] * ((a1 - b1) / cnt) +
                          (double)w[2] * ((a2 - b2) / cnt);
            out[0] = (float)loss;
            g_done = 0u;                      // reset for next graph replay
        }
    }
}

extern "C" void kernel_launch(void* const* d_in, const int* in_sizes, int n_in,
                              void* d_out, int out_size) {
    (void)n_in; (void)out_size;
    int iopt[3], ihist[3], imin[3], imax[3];
    if (in_sizes[1] == kC * kBins) {       // dict (interleaved) order
        for (int l = 0; l < 3; l++) { iopt[l] = 4*l; ihist[l] = 4*l+1; imin[l] = 4*l+2; imax[l] = 4*l+3; }
    } else {                               // signature order
        for (int l = 0; l < 3; l++) { iopt[l] = l; ihist[l] = 3+l; imin[l] = 6+l; imax[l] = 9+l; }
    }
    const int iw = 12, imask = 13;

    static int smem_set = 0;
    if (!smem_set) {
        cudaFuncSetAttribute(fused_kernel, cudaFuncAttributeMaxDynamicSharedMemorySize,
                             3 * kB * sizeof(unsigned int));
        smem_set = 1;
    }

    fused_kernel<<<kSegs, 1024, 3 * kB * sizeof(unsigned int)>>>(
        (const float*)d_in[iopt[0]], (const float*)d_in[iopt[1]], (const float*)d_in[iopt[2]],
        (const float*)d_in[ihist[0]], (const float*)d_in[ihist[1]], (const float*)d_in[ihist[2]],
        (const float*)d_in[imin[0]], (const float*)d_in[imin[1]], (const float*)d_in[imin[2]],
        (const float*)d_in[imax[0]], (const float*)d_in[imax[1]], (const float*)d_in[imax[2]],
        (const int*)d_in[imask], (const float*)d_in[iw], (float*)d_out);
}